// round 16
// baseline (speedup 1.0000x reference)
#include <cuda_runtime.h>
#include <cstdint>

#define DK 128
#define BB 128
#define SS 128
#define NQ 101

// ---------------- device-global scratch (no runtime allocation) ----------------
__device__ float g_P2[BB * SS * DK];
__device__ float g_P3[BB * SS * DK];
__device__ float g_P4[BB * SS * DK];
__device__ float g_P5[BB * SS * DK];
__device__ uint32_t g_Wab[11 * 8192];  // bf16x2 A-frag layout: kt*1024 + d*8 + (kw&7)
__device__ uint32_t g_Wz[16384];       // W2d/W3d stacked 256-row A-frag: kt*2048 + dz*8 + (kw&7)
__device__ uint32_t g_Wkp[2 * 8192];   // bf16x2 k-pair layout: kw*128 + d  (0=W4b 1=W5b)
__device__ float g_r1[DK];             // rowsum of W1[:,256:384]

// g_Wab slice ids
#define SL_W1a 0
#define SL_W1b 1
#define SL_W2a 2
#define SL_W2b 3
#define SL_W2c 4
#define SL_W3a 5
#define SL_W3b 6
#define SL_W3c 7
#define SL_W4c 8
#define SL_W5a 9
#define SL_W4a 10

__device__ __forceinline__ float fast_tanh(float x) {
    float y;
    asm("tanh.approx.f32 %0, %1;" : "=f"(y) : "f"(x));
    return y;
}
__device__ __forceinline__ float fast_sigmoid(float x) {
    return fmaf(fast_tanh(x * 0.5f), 0.5f, 0.5f);
}

__device__ __forceinline__ uint32_t pack_bf16(float lo, float hi) {
    uint32_t r;
    asm("cvt.rn.bf16x2.f32 %0, %1, %2;" : "=r"(r) : "f"(hi), "f"(lo));
    return r;
}
__device__ __forceinline__ float bf_lo(uint32_t w) { return __uint_as_float(w << 16); }
__device__ __forceinline__ float bf_hi(uint32_t w) { return __uint_as_float(w & 0xFFFF0000u); }
__device__ __forceinline__ uint16_t bf16_of(float v) { return (uint16_t)pack_bf16(v, 0.f); }

// bf16 mma m16n8k16: D += A(16x16 row) * B(16x8 col), fp32 acc
__device__ __forceinline__ void mma16(float* acc, const uint32_t* a, uint32_t b0, uint32_t b1) {
    asm volatile(
        "mma.sync.aligned.m16n8k16.row.col.f32.bf16.bf16.f32 "
        "{%0,%1,%2,%3}, {%4,%5,%6,%7}, {%8,%9}, {%0,%1,%2,%3};"
        : "+f"(acc[0]), "+f"(acc[1]), "+f"(acc[2]), "+f"(acc[3])
        : "r"(a[0]), "r"(a[1]), "r"(a[2]), "r"(a[3]), "r"(b0), "r"(b1));
}

// ---------------- k_transpose: build bf16 weight tables + r1 ----------------
__global__ void k_transpose(const float* __restrict__ W1, const float* __restrict__ W2,
                            const float* __restrict__ W3, const float* __restrict__ W4,
                            const float* __restrict__ W5) {
    int m = blockIdx.x, tid = threadIdx.x;
    const float* src; int ld, off;
    switch (m) {
        case 0:  src = W1; ld = 384; off = 0;   break;  // W1a
        case 1:  src = W1; ld = 384; off = 128; break;  // W1b
        case 2:  src = W2; ld = 512; off = 0;   break;  // W2a
        case 3:  src = W2; ld = 512; off = 128; break;  // W2b
        case 4:  src = W2; ld = 512; off = 256; break;  // W2c
        case 5:  src = W3; ld = 512; off = 0;   break;  // W3a
        case 6:  src = W3; ld = 512; off = 128; break;  // W3b
        case 7:  src = W3; ld = 512; off = 256; break;  // W3c
        case 8:  src = W4; ld = 384; off = 256; break;  // W4c
        case 9:  src = W5; ld = 256; off = 0;   break;  // W5a
        case 10: src = W4; ld = 384; off = 0;   break;  // W4a
        case 11: src = W2; ld = 512; off = 384; break;  // W2d -> g_Wz rows 0..127
        case 12: src = W3; ld = 512; off = 384; break;  // W3d -> g_Wz rows 128..255
        case 13: src = W4; ld = 384; off = 128; break;  // W4b -> g_Wkp[0]
        default: src = W5; ld = 256; off = 128; break;  // W5b -> g_Wkp[1]
    }
    if (m < 11) {
        uint32_t* dst = g_Wab + m * 8192;
        for (int i = tid; i < 8192; i += 256) {
            int d = i >> 6, kw = i & 63;
            dst[(kw >> 3) * 1024 + d * 8 + (kw & 7)] =
                pack_bf16(src[d * ld + off + 2 * kw], src[d * ld + off + 2 * kw + 1]);
        }
    } else if (m < 13) {
        for (int i = tid; i < 8192; i += 256) {
            int d = i >> 6, kw = i & 63;
            int dz = d + (m - 11) * 128;
            g_Wz[(kw >> 3) * 2048 + dz * 8 + (kw & 7)] =
                pack_bf16(src[d * ld + off + 2 * kw], src[d * ld + off + 2 * kw + 1]);
        }
    } else {
        uint32_t* dst = g_Wkp + (m - 13) * 8192;
        for (int i = tid; i < 8192; i += 256) {
            int kw = i >> 7, d = i & 127;
            dst[i] = pack_bf16(src[d * ld + off + 2 * kw], src[d * ld + off + 2 * kw + 1]);
        }
    }
    if (m == 0) {
        for (int d = tid; d < DK; d += 256) {
            float s = 0.f;
            for (int j = 0; j < 128; j++) s += W1[d * 384 + 256 + j];
            g_r1[d] = s;
        }
    }
}

// ---------------- k_pre: AL + P2..P5 via bf16 tensor MMA ----------------
#define PB_W    9956
#define PRE_SB0 0
#define PRE_SB1 9956
#define PRE_SB2 19912
#define PRE_STG 29868
#define PRE_EI  46764
#define PRE_AI  46892
#define PRE_II  47020
#define PRE_AF  47148
#define PRE_B1  47276
#define PRE_B2  47404
#define PRE_B3  47532
#define PRE_B4  47660
#define PRE_B5  47788
#define PRE_R1  47916
#define PRE_SMEM_BYTES (48044 * 4)

__device__ __forceinline__ void gemm_pass(float (&acc)[16][4], const uint32_t* __restrict__ gA,
                                          const uint32_t* sB, int rowoff, int dwu, int u, int r) {
    const uint32_t* Bb = sB + (u + rowoff) * 76 + r;
    for (int kt = 0; kt < 8; kt++) {
        uint32_t a4[4];
        int ai = kt * 1024 + dwu + r;
        a4[0] = gA[ai]; a4[1] = gA[ai + 64]; a4[2] = gA[ai + 4]; a4[3] = gA[ai + 68];
        const uint32_t* Bk = Bb + kt * 8;
#pragma unroll
        for (int nt = 0; nt < 16; nt++)
            mma16(acc[nt], a4, Bk[nt * 608], Bk[nt * 608 + 4]);
    }
}

__device__ __forceinline__ void acc_zero16(float (&acc)[16][4]) {
#pragma unroll
    for (int nt = 0; nt < 16; nt++) {
        acc[nt][0] = 0.f; acc[nt][1] = 0.f; acc[nt][2] = 0.f; acc[nt][3] = 0.f;
    }
}

__device__ __forceinline__ void stage_epi(const float (&acc)[16][4], const float* bs,
                                          int d0, int r, float* stg) {
    float bb0 = bs[d0], bb1 = bs[d0 + 8];
#pragma unroll
    for (int nt = 0; nt < 16; nt++) {
        int t0 = 8 * nt + 2 * r;
        stg[t0 * 132 + d0]           = acc[nt][0] + bb0;
        stg[(t0 + 1) * 132 + d0]     = acc[nt][1] + bb0;
        stg[t0 * 132 + d0 + 8]       = acc[nt][2] + bb1;
        stg[(t0 + 1) * 132 + d0 + 8] = acc[nt][3] + bb1;
    }
}

__device__ __forceinline__ void copy_out(const float* stg, float* __restrict__ dst, int tid) {
#pragma unroll
    for (int j = 0; j < 16; j++) {
        int lin = (j * 256 + tid) * 4;
        int t = lin >> 7, d = lin & 127;
        float4 v = *(const float4*)(stg + t * 132 + d);
        *(float4*)(dst + lin) = v;
    }
}

__global__ void __launch_bounds__(256, 1) k_pre(const int* __restrict__ e_data,
                                                const int* __restrict__ a_data,
                                                const int* __restrict__ it_data,
                                                const int* __restrict__ at_data,
                                                const float* __restrict__ e_w,
                                                const float* __restrict__ at_w,
                                                const float* __restrict__ it_w,
                                                const float* __restrict__ b1,
                                                const float* __restrict__ b2,
                                                const float* __restrict__ b3,
                                                const float* __restrict__ b4,
                                                const float* __restrict__ b5) {
    extern __shared__ uint32_t ps[];
    uint32_t* sB0 = ps + PRE_SB0;
    uint32_t* sB1 = ps + PRE_SB1;
    uint32_t* sB2 = ps + PRE_SB2;
    float* stg  = (float*)(ps + PRE_STG);
    int*   s_ei = (int*)(ps + PRE_EI);
    int*   s_ai = (int*)(ps + PRE_AI);
    int*   s_ii = (int*)(ps + PRE_II);
    float* s_af = (float*)(ps + PRE_AF);
    float* b1s  = (float*)(ps + PRE_B1);
    float* b2s  = (float*)(ps + PRE_B2);
    float* b3s  = (float*)(ps + PRE_B3);
    float* b4s  = (float*)(ps + PRE_B4);
    float* b5s  = (float*)(ps + PRE_B5);
    float* r1s  = (float*)(ps + PRE_R1);

    const int b = blockIdx.x, tid = threadIdx.x;
    const int w = tid >> 5, l = tid & 31, u = l >> 2, r = l & 3;
    const int d0 = 16 * w + u;
    const int dwu = d0 * 8;

    if (tid < 128) {
        s_ei[tid] = e_data[b * SS + tid];
        s_ai[tid] = at_data[b * SS + tid];
        s_ii[tid] = it_data[b * SS + tid];
        s_af[tid] = (float)a_data[b * SS + tid];
        b1s[tid] = b1[tid]; b2s[tid] = b2[tid]; b3s[tid] = b3[tid];
        b4s[tid] = b4[tid]; b5s[tid] = b5[tid];
        r1s[tid] = g_r1[tid];
    }
    for (int i = tid; i < 3 * 76; i += 256) {
        int rr = i / 76, cc = i % 76;
        int wd = (rr == 0 ? 0 : (rr == 1 ? 129 : 130)) * 76 + cc;
        sB0[wd] = 0u; sB1[wd] = 0u; sB2[wd] = 0u;
    }
    __syncthreads();
    for (int i = tid; i < 8192; i += 256) {
        int n = i >> 6, kw = i & 63;
        int wd = (n + 1) * 76 + kw;
        float2 ev = *(const float2*)(e_w + s_ei[n] * DK + 2 * kw);
        float2 av = *(const float2*)(at_w + s_ai[n] * DK + 2 * kw);
        float2 iv = *(const float2*)(it_w + s_ii[n] * DK + 2 * kw);
        sB0[wd] = pack_bf16(ev.x, ev.y);
        sB1[wd] = pack_bf16(av.x, av.y);
        sB2[wd] = pack_bf16(iv.x, iv.y);
    }
    __syncthreads();

    float acc[16][4];
    acc_zero16(acc);
    gemm_pass(acc, g_Wab + SL_W1a * 8192, sB0, 1, dwu, u, r);
    gemm_pass(acc, g_Wab + SL_W1b * 8192, sB1, 1, dwu, u, r);
    __syncthreads();
    {
        float bb0 = b1s[d0], bb1 = b1s[d0 + 8];
        float rr0 = r1s[d0], rr1 = r1s[d0 + 8];
        char* base = (char*)sB1;
        int byc = 4 * (d0 >> 1) + 2 * (d0 & 1);
#pragma unroll
        for (int nt = 0; nt < 16; nt++) {
            int t0 = 8 * nt + 2 * r;
            float a0f = s_af[t0], a1f = s_af[t0 + 1];
            float v00 = acc[nt][0] + bb0 + a0f * rr0;
            float v01 = acc[nt][1] + bb0 + a1f * rr0;
            float v10 = acc[nt][2] + bb1 + a0f * rr1;
            float v11 = acc[nt][3] + bb1 + a1f * rr1;
            int by = (t0 + 1) * 304 + byc;
            *(uint16_t*)(base + by)        = bf16_of(v00);
            *(uint16_t*)(base + by + 304)  = bf16_of(v01);
            *(uint16_t*)(base + by + 16)   = bf16_of(v10);
            *(uint16_t*)(base + by + 320)  = bf16_of(v11);
        }
    }
    __syncthreads();

    acc_zero16(acc);
    gemm_pass(acc, g_Wab + SL_W2a * 8192, sB1, 0, dwu, u, r);
    gemm_pass(acc, g_Wab + SL_W2b * 8192, sB2, 1, dwu, u, r);
    gemm_pass(acc, g_Wab + SL_W2c * 8192, sB1, 1, dwu, u, r);
    stage_epi(acc, b2s, d0, r, stg);
    __syncthreads();
    copy_out(stg, g_P2 + b * SS * DK, tid);
    __syncthreads();

    acc_zero16(acc);
    gemm_pass(acc, g_Wab + SL_W3a * 8192, sB1, 0, dwu, u, r);
    gemm_pass(acc, g_Wab + SL_W3b * 8192, sB2, 1, dwu, u, r);
    gemm_pass(acc, g_Wab + SL_W3c * 8192, sB1, 1, dwu, u, r);
    stage_epi(acc, b3s, d0, r, stg);
    __syncthreads();
    copy_out(stg, g_P3 + b * SS * DK, tid);
    __syncthreads();

    acc_zero16(acc);
    gemm_pass(acc, g_Wab + SL_W4c * 8192, sB2, 1, dwu, u, r);
    stage_epi(acc, b4s, d0, r, stg);
    __syncthreads();
    copy_out(stg, g_P4 + b * SS * DK, tid);
    __syncthreads();

    acc_zero16(acc);
    gemm_pass(acc, g_Wab + SL_W5a * 8192, sB0, 2, dwu, u, r);
    stage_epi(acc, b5s, d0, r, stg);
    __syncthreads();
    copy_out(stg, g_P5 + b * SS * DK, tid);
}

// ---------------- main scan kernel (512 threads) ----------------
// SMEM bytes:
//  Hsb   [0, 38912)          bf16x2 H shadow, word(n,kw)=n*76+kw
//  sWab  [38912, 71680)      W4a A-frag
//  sWz   [71680, 137216)     W2d/W3d stacked 256-row A-frag
//  sW4b  [137216, 169984)    k-pair
//  sW5b  [169984, 202752)    k-pair
//  ht[202752] LG[203264] htb[203776,256) pA3[204032,512) arg[204544,2048)
//  qe[206592] qn[207104] htp[207616,1024) red[208640,64)
#define HSB_B   0
#define SWAB_B  38912
#define SWZ_B   71680
#define SW4B_B  137216
#define SW5B_B  169984
#define HT_B    202752
#define LG_B    203264
#define HTB_B   203776
#define PA3_B   204032
#define ARG_B   204544
#define QE_B    206592
#define QN_B    207104
#define HTP_B   207616
#define RED_B   208640
#define SMEM_MAIN_BYTES 208704

template<int NT>
__device__ __forceinline__ void s4a_mma(float (&acc)[8][4], const uint32_t* sWab,
                                        const uint32_t* HsbH, int da, int r, int btw) {
    for (int kt = 0; kt < 8; kt++) {
        uint32_t a4[4];
        int ab = kt * 1024 + da * 8 + r;
        a4[0] = sWab[ab];
        a4[1] = sWab[ab + 64];
        a4[2] = sWab[ab + 4];
        a4[3] = sWab[ab + 68];
        const uint32_t* Hk = HsbH + btw + kt * 8;
#pragma unroll
        for (int nt = 0; nt < NT; nt++)
            mma16(acc[nt], a4, Hk[nt * 608], Hk[nt * 608 + 4]);
    }
}

template<int NT>
__device__ __forceinline__ void epi_step(float (&acc)[8][4], float (&Hreg)[8][4],
                                         const float* arg, const float* LG,
                                         const float* qe, const float* qn,
                                         char* smc, float* htp,
                                         int da, int h, int r, int hb0) {
    float cs0 = (arg[da] + arg[128 + da]) + (arg[256 + da] + arg[384 + da]);
    float cs1 = (arg[da + 8] + arg[128 + da + 8]) + (arg[256 + da + 8] + arg[384 + da + 8]);
    float lg0 = LG[da], lg1 = LG[da + 8];
    float s0 = 0.f, s1 = 0.f;
#pragma unroll
    for (int nt = 0; nt < NT; nt++) {
        int n0 = 64 * h + 8 * nt + 2 * r;
        float2 qev = *(const float2*)(qe + n0);
        float2 qnv2 = *(const float2*)(qn + n0);
        float H00 = qev.x * lg0 + fast_sigmoid(acc[nt][0] + cs0) * Hreg[nt][0];
        float H01 = qev.y * lg0 + fast_sigmoid(acc[nt][1] + cs0) * Hreg[nt][1];
        float H10 = qev.x * lg1 + fast_sigmoid(acc[nt][2] + cs1) * Hreg[nt][2];
        float H11 = qev.y * lg1 + fast_sigmoid(acc[nt][3] + cs1) * Hreg[nt][3];
        Hreg[nt][0] = H00; Hreg[nt][1] = H01;
        Hreg[nt][2] = H10; Hreg[nt][3] = H11;
        int bn = hb0 + 2432 * nt;
        *(uint16_t*)(smc + bn)       = bf16_of(H00);
        *(uint16_t*)(smc + bn + 16)  = bf16_of(H10);
        *(uint16_t*)(smc + bn + 304) = bf16_of(H01);
        *(uint16_t*)(smc + bn + 320) = bf16_of(H11);
        s0 = fmaf(qnv2.x, H00, fmaf(qnv2.y, H01, s0));
        s1 = fmaf(qnv2.x, H10, fmaf(qnv2.y, H11, s1));
    }
    s0 += __shfl_xor_sync(0xffffffffu, s0, 1);
    s0 += __shfl_xor_sync(0xffffffffu, s0, 2);
    s1 += __shfl_xor_sync(0xffffffffu, s1, 1);
    s1 += __shfl_xor_sync(0xffffffffu, s1, 2);
    if (r == 0) {
        htp[h * 128 + da]     = s0;
        htp[h * 128 + da + 8] = s1;
    }
}

__global__ void __launch_bounds__(512, 1) k_main(const int* __restrict__ e_data,
                                                 const float* __restrict__ qm,
                                                 const float* __restrict__ h0,
                                                 float* __restrict__ out) {
    extern __shared__ char smc[];
    uint32_t* Hsb  = (uint32_t*)(smc + HSB_B);
    uint32_t* sWab = (uint32_t*)(smc + SWAB_B);
    uint32_t* sWz  = (uint32_t*)(smc + SWZ_B);
    uint32_t* sW4b = (uint32_t*)(smc + SW4B_B);
    uint32_t* sW5b = (uint32_t*)(smc + SW5B_B);
    float*    ht   = (float*)(smc + HT_B);
    float*    LG   = (float*)(smc + LG_B);
    uint32_t* htb  = (uint32_t*)(smc + HTB_B);
    float*    pA3  = (float*)(smc + PA3_B);
    float*    arg  = (float*)(smc + ARG_B);
    float*    qe   = (float*)(smc + QE_B);
    float*    qn   = (float*)(smc + QN_B);
    float*    htp  = (float*)(smc + HTP_B);
    float*    red  = (float*)(smc + RED_B);

    const int b = blockIdx.x, tid = threadIdx.x;
    const int w = tid >> 5, l = tid & 31;
    const int u = l >> 2, r = l & 3;
    const int o = w & 7;                 // d-oct: d in {16o+u, 16o+u+8}
    const int h = w >> 3;                // n-half
    const int da = 16 * o + u;

    // ---- SMEM init ----
    for (int i = tid; i < 8192; i += 512) {
        sWab[i] = g_Wab[SL_W4a * 8192 + i];
        sW4b[i] = g_Wkp[i];
        sW5b[i] = g_Wkp[8192 + i];
    }
    for (int i = tid; i < 16384; i += 512) sWz[i] = g_Wz[i];
    for (int i = tid; i < 8192; i += 512) {
        int n = i >> 6, kw = i & 63;
        float v0 = (n < NQ) ? h0[n * DK + 2 * kw] : 0.f;
        float v1 = (n < NQ) ? h0[n * DK + 2 * kw + 1] : 0.f;
        Hsb[n * 76 + kw] = pack_bf16(v0, v1);
    }
    float Hreg[8][4];
#pragma unroll
    for (int nt = 0; nt < 8; nt++) {
        int n0 = 64 * h + 8 * nt + 2 * r;
        Hreg[nt][0] = (n0 < NQ)     ? h0[n0 * DK + da]           : 0.f;
        Hreg[nt][1] = (n0 + 1 < NQ) ? h0[(n0 + 1) * DK + da]     : 0.f;
        Hreg[nt][2] = (n0 < NQ)     ? h0[n0 * DK + da + 8]       : 0.f;
        Hreg[nt][3] = (n0 + 1 < NQ) ? h0[(n0 + 1) * DK + da + 8] : 0.f;
    }

    int eA = e_data[b * SS];
    int eB = e_data[b * SS + 1];
    if (tid < 128) {
        qe[tid] = (tid < NQ) ? qm[eA * NQ + tid] : 0.f;
        qn[tid] = 0.f;
    }
    __syncthreads();
    if (tid < 32) {
        float v = 0.f;
        for (int n = tid; n < NQ; n += 32) v += qe[n];
#pragma unroll
        for (int oo = 16; oo; oo >>= 1) v += __shfl_xor_sync(0xffffffffu, v, oo);
        if (tid == 0) red[0] = v;
    }
    __syncthreads();
    if (tid < 128) {
        float a = 0.f;
        for (int n = 0; n < NQ; n++) a += qe[n] * h0[n * DK + tid];
        ht[tid] = a / red[0];
    }
    if (tid == 0) out[b * SS] = 0.f;
    __syncthreads();
    if (tid < 64) htb[tid] = pack_bf16(ht[2 * tid], ht[2 * tid + 1]);

    // ---- prefetch step-0 operands ----
    float p_a = 0.f, p4v = 0.f, p5v = 0.f, qv = 0.f, qnv = 0.f;
    {
        const int base = (b * SS) * DK;
        if (tid < 128) {
            p_a = g_P2[base + tid];
            p4v = g_P4[base + tid];
            p5v = g_P5[base + tid];
            qv  = (tid < NQ) ? qm[eA * NQ + tid] : 0.f;
        } else if (tid < 256) {
            p_a = g_P3[base + tid - 128];
            int m = tid - 128;
            qnv = (m < NQ) ? qm[eB * NQ + m] : 0.f;
        }
    }

    const int btw = u * 76 + r;
    const uint32_t* HsbH = Hsb + h * 4864;
    const int hb0 = 304 * (64 * h + 2 * r) + 2 * da;
    const int zbase = 128 * w + 8 * u + r;      // S1-MMA A-frag base (16 rows/warp)

    // ---- scan ----
    for (int t = 0; t < SS - 1; t++) {
        __syncthreads();                        // sync1
        if (tid < 128) qe[tid] = qv;
        else if (tid < 256) { qn[tid - 128] = qnv; pA3[tid - 128] = p_a; }
        if (tid == 0 && t > 0)
            out[b * SS + t] = (red[8] + red[9] + red[10] + red[11]) * (1.0f / 128.0f);

        // S1-MMA: arg[0..255] = Wz . ht  (16 rows/warp)
        {
            float z0[4] = {0.f, 0.f, 0.f, 0.f};
            for (int kt = 0; kt < 8; kt++) {
                const uint32_t* Wk = sWz + kt * 2048;
                uint32_t az[4];
                az[0] = Wk[zbase];      az[1] = Wk[zbase + 64];
                az[2] = Wk[zbase + 4];  az[3] = Wk[zbase + 68];
                uint32_t hb_0 = (u == 0) ? htb[kt * 8 + r] : 0u;
                uint32_t hb_1 = (u == 0) ? htb[kt * 8 + r + 4] : 0u;
                mma16(z0, az, hb_0, hb_1);
            }
            if (r == 0) {
                arg[16 * w + u]     = z0[0];
                arg[16 * w + u + 8] = z0[2];
            }
        }

        // S4a: bf16 tensor GEMM (16 d x 64 n per warp; h=1 trimmed to 5 tiles)
        float acc[8][4];
#pragma unroll
        for (int nt = 0; nt < 8; nt++) {
            acc[nt][0] = 0.f; acc[nt][1] = 0.f; acc[nt][2] = 0.f; acc[nt][3] = 0.f;
        }
        if (h == 0) s4a_mma<8>(acc, sWab, HsbH, da, r, btw);
        else        s4a_mma<5>(acc, sWab, HsbH, da, r, btw);
        __syncthreads();                        // sync2

        // S2 (tid<128): LG  || qn-sum (tid 128..159)
        if (tid < 128) {
            float lg = fast_tanh(arg[tid] + p_a);
            float gl = fast_sigmoid(arg[128 + tid] + pA3[tid]);
            LG[tid] = gl * (lg + 1.f) * 0.5f;
        } else if (tid < 160) {
            int lane = tid - 128;
            float v = 0.f;
            for (int n = lane; n < NQ; n += 32) v += qn[n];
#pragma unroll
            for (int oo = 16; oo; oo >>= 1) v += __shfl_xor_sync(0xffffffffu, v, oo);
            if (lane == 0) red[0] = v;
        }
        __syncthreads();                        // sync3

        // S3: split-k x4 partials of P4 + LG @ W4b^T  -> arg[qq*128+d]
        {
            int d = tid & 127, qq = tid >> 7;
            const uint32_t* Wp = sW4b + qq * 16 * 128;
            const float* lgp = LG + qq * 32;
            float a0 = (qq == 0) ? p4v : 0.f, a1 = 0.f, a2 = 0.f, a3 = 0.f;
#pragma unroll
            for (int kw = 0; kw < 16; kw += 2) {
                uint32_t w0 = Wp[kw * 128 + d];
                uint32_t w1 = Wp[(kw + 1) * 128 + d];
                float4 lv = *(const float4*)(lgp + 2 * kw);
                a0 = fmaf(lv.x, bf_lo(w0), a0);
                a1 = fmaf(lv.y, bf_hi(w0), a1);
                a2 = fmaf(lv.z, bf_lo(w1), a2);
                a3 = fmaf(lv.w, bf_hi(w1), a3);
            }
            arg[tid] = (a0 + a1) + (a2 + a3);
        }
        __syncthreads();                        // sync4

        // S4b epilogue (cS combined from 4 partials inline)
        if (h == 0) epi_step<8>(acc, Hreg, arg, LG, qe, qn, smc, htp, da, h, r, hb0);
        else        epi_step<5>(acc, Hreg, arg, LG, qe, qn, smc, htp, da, h, r, hb0);
        __syncthreads();                        // sync5

        if (tid < 128) ht[tid] = (htp[tid] + htp[128 + tid]) / red[0];

        // prefetch next step operands
        float p5cur = p5v;
        {
            int t2 = (t + 2 < SS) ? t + 2 : SS - 1;
            eA = eB;
            eB = e_data[b * SS + t2];
            const int base2 = (b * SS + t + 1) * DK;
            if (tid < 128) {
                p_a = g_P2[base2 + tid];
                p4v = g_P4[base2 + tid];
                p5v = g_P5[base2 + tid];
                qv  = (tid < NQ) ? qm[eA * NQ + tid] : 0.f;
            } else if (tid < 256) {
                p_a = g_P3[base2 + tid - 128];
                int m = tid - 128;
                qnv = (m < NQ) ? qm[eB * NQ + m] : 0.f;
            }
        }
        __syncthreads();                        // sync6

        if (tid < 64) htb[tid] = pack_bf16(ht[2 * tid], ht[2 * tid + 1]);

        // S6: split-k x4 partials of P5 + ht @ W5b^T -> arg[qq*128+d]
        {
            int d = tid & 127, qq = tid >> 7;
            const uint32_t* Wp = sW5b + qq * 16 * 128;
            const float* hp = ht + qq * 32;
            float a0 = (qq == 0) ? p5cur : 0.f, a1 = 0.f, a2 = 0.f, a3 = 0.f;
#pragma unroll
            for (int kw = 0; kw < 16; kw += 2) {
                uint32_t w0 = Wp[kw * 128 + d];
                uint32_t w1 = Wp[(kw + 1) * 128 + d];
                float4 hv = *(const float4*)(hp + 2 * kw);
                a0 = fmaf(hv.x, bf_lo(w0), a0);
                a1 = fmaf(hv.y, bf_hi(w0), a1);
                a2 = fmaf(hv.z, bf_lo(w1), a2);
                a3 = fmaf(hv.w, bf_hi(w1), a3);
            }
            arg[tid] = (a0 + a1) + (a2 + a3);
        }
        __syncthreads();                        // sync7
        float v = 0.f;
        if (tid < 128)
            v = fast_sigmoid((arg[tid] + arg[128 + tid]) + (arg[256 + tid] + arg[384 + tid]));
#pragma unroll
        for (int oo = 16; oo; oo >>= 1) v += __shfl_xor_sync(0xffffffffu, v, oo);
        if (tid < 128 && l == 0) red[8 + w] = v;
        // no sync8: out written after next sync1
    }
    __syncthreads();
    if (tid == 0)
        out[b * SS + SS - 1] = (red[8] + red[9] + red[10] + red[11]) * (1.0f / 128.0f);
}

// ---------------- host launcher ----------------
extern "C" void kernel_launch(void* const* d_in, const int* in_sizes, int n_in,
                              void* d_out, int out_size) {
    (void)in_sizes; (void)n_in; (void)out_size;
    const int*   e_data  = (const int*)d_in[0];
    const int*   a_data  = (const int*)d_in[1];
    const int*   it_data = (const int*)d_in[2];
    const int*   at_data = (const int*)d_in[3];
    const float* qm      = (const float*)d_in[4];
    const float* e_w     = (const float*)d_in[5];
    const float* at_w    = (const float*)d_in[6];
    const float* it_w    = (const float*)d_in[7];
    const float* h0      = (const float*)d_in[8];
    const float* W1      = (const float*)d_in[9];
    const float* b1      = (const float*)d_in[10];
    const float* W2      = (const float*)d_in[11];
    const float* b2      = (const float*)d_in[12];
    const float* W3      = (const float*)d_in[13];
    const float* b3      = (const float*)d_in[14];
    const float* W4      = (const float*)d_in[15];
    const float* b4      = (const float*)d_in[16];
    const float* W5      = (const float*)d_in[17];
    const float* b5      = (const float*)d_in[18];
    float* out = (float*)d_out;

    cudaFuncSetAttribute(k_pre,  cudaFuncAttributeMaxDynamicSharedMemorySize, PRE_SMEM_BYTES);
    cudaFuncSetAttribute(k_main, cudaFuncAttributeMaxDynamicSharedMemorySize, SMEM_MAIN_BYTES);

    k_transpose<<<15, 256>>>(W1, W2, W3, W4, W5);
    k_pre<<<BB, 256, PRE_SMEM_BYTES>>>(e_data, a_data, it_data, at_data,
                                       e_w, at_w, it_w, b1, b2, b3, b4, b5);
    k_main<<<BB, 512, SMEM_MAIN_BYTES>>>(e_data, qm, h0, out);
    (void)W4;
}

// round 17
// speedup vs baseline: 1.1041x; 1.1041x over previous
#include <cuda_runtime.h>
#include <cstdint>

#define DK 128
#define BB 128
#define SS 128
#define NQ 101

// ---------------- device-global scratch (no runtime allocation) ----------------
__device__ float g_P2[BB * SS * DK];
__device__ float g_P3[BB * SS * DK];
__device__ float g_P4[BB * SS * DK];
__device__ float g_P5[BB * SS * DK];
__device__ uint32_t g_Wab[11 * 8192];  // bf16x2 A-frag layout: kt*1024 + d*8 + (kw&7)
__device__ uint32_t g_Wz[16384];       // W2d/W3d stacked 256-row A-frag: kt*2048 + dz*8 + (kw&7)
__device__ uint32_t g_Wkp[2 * 8192];   // bf16x2 k-pair layout: kw*128 + d  (0=W4b 1=W5b)
__device__ float g_r1[DK];             // rowsum of W1[:,256:384]

// g_Wab slice ids
#define SL_W1a 0
#define SL_W1b 1
#define SL_W2a 2
#define SL_W2b 3
#define SL_W2c 4
#define SL_W3a 5
#define SL_W3b 6
#define SL_W3c 7
#define SL_W4c 8
#define SL_W5a 9
#define SL_W4a 10

__device__ __forceinline__ float fast_tanh(float x) {
    float y;
    asm("tanh.approx.f32 %0, %1;" : "=f"(y) : "f"(x));
    return y;
}
__device__ __forceinline__ float fast_sigmoid(float x) {
    return fmaf(fast_tanh(x * 0.5f), 0.5f, 0.5f);
}

__device__ __forceinline__ uint32_t pack_bf16(float lo, float hi) {
    uint32_t r;
    asm("cvt.rn.bf16x2.f32 %0, %1, %2;" : "=r"(r) : "f"(hi), "f"(lo));
    return r;
}
__device__ __forceinline__ float bf_lo(uint32_t w) { return __uint_as_float(w << 16); }
__device__ __forceinline__ float bf_hi(uint32_t w) { return __uint_as_float(w & 0xFFFF0000u); }
__device__ __forceinline__ uint16_t bf16_of(float v) { return (uint16_t)pack_bf16(v, 0.f); }

// bf16 mma m16n8k16: D += A(16x16 row) * B(16x8 col), fp32 acc
__device__ __forceinline__ void mma16(float* acc, const uint32_t* a, uint32_t b0, uint32_t b1) {
    asm volatile(
        "mma.sync.aligned.m16n8k16.row.col.f32.bf16.bf16.f32 "
        "{%0,%1,%2,%3}, {%4,%5,%6,%7}, {%8,%9}, {%0,%1,%2,%3};"
        : "+f"(acc[0]), "+f"(acc[1]), "+f"(acc[2]), "+f"(acc[3])
        : "r"(a[0]), "r"(a[1]), "r"(a[2]), "r"(a[3]), "r"(b0), "r"(b1));
}

// ---------------- k_transpose: build bf16 weight tables + r1 ----------------
__global__ void k_transpose(const float* __restrict__ W1, const float* __restrict__ W2,
                            const float* __restrict__ W3, const float* __restrict__ W4,
                            const float* __restrict__ W5) {
    int m = blockIdx.x, tid = threadIdx.x;
    const float* src; int ld, off;
    switch (m) {
        case 0:  src = W1; ld = 384; off = 0;   break;  // W1a
        case 1:  src = W1; ld = 384; off = 128; break;  // W1b
        case 2:  src = W2; ld = 512; off = 0;   break;  // W2a
        case 3:  src = W2; ld = 512; off = 128; break;  // W2b
        case 4:  src = W2; ld = 512; off = 256; break;  // W2c
        case 5:  src = W3; ld = 512; off = 0;   break;  // W3a
        case 6:  src = W3; ld = 512; off = 128; break;  // W3b
        case 7:  src = W3; ld = 512; off = 256; break;  // W3c
        case 8:  src = W4; ld = 384; off = 256; break;  // W4c
        case 9:  src = W5; ld = 256; off = 0;   break;  // W5a
        case 10: src = W4; ld = 384; off = 0;   break;  // W4a
        case 11: src = W2; ld = 512; off = 384; break;  // W2d -> g_Wz rows 0..127
        case 12: src = W3; ld = 512; off = 384; break;  // W3d -> g_Wz rows 128..255
        case 13: src = W4; ld = 384; off = 128; break;  // W4b -> g_Wkp[0]
        default: src = W5; ld = 256; off = 128; break;  // W5b -> g_Wkp[1]
    }
    if (m < 11) {
        uint32_t* dst = g_Wab + m * 8192;
        for (int i = tid; i < 8192; i += 256) {
            int d = i >> 6, kw = i & 63;
            dst[(kw >> 3) * 1024 + d * 8 + (kw & 7)] =
                pack_bf16(src[d * ld + off + 2 * kw], src[d * ld + off + 2 * kw + 1]);
        }
    } else if (m < 13) {
        for (int i = tid; i < 8192; i += 256) {
            int d = i >> 6, kw = i & 63;
            int dz = d + (m - 11) * 128;
            g_Wz[(kw >> 3) * 2048 + dz * 8 + (kw & 7)] =
                pack_bf16(src[d * ld + off + 2 * kw], src[d * ld + off + 2 * kw + 1]);
        }
    } else {
        uint32_t* dst = g_Wkp + (m - 13) * 8192;
        for (int i = tid; i < 8192; i += 256) {
            int kw = i >> 7, d = i & 127;
            dst[i] = pack_bf16(src[d * ld + off + 2 * kw], src[d * ld + off + 2 * kw + 1]);
        }
    }
    if (m == 0) {
        for (int d = tid; d < DK; d += 256) {
            float s = 0.f;
            for (int j = 0; j < 128; j++) s += W1[d * 384 + 256 + j];
            g_r1[d] = s;
        }
    }
}

// ---------------- k_pre: AL + P2..P5 via bf16 tensor MMA ----------------
#define PB_W    9956
#define PRE_SB0 0
#define PRE_SB1 9956
#define PRE_SB2 19912
#define PRE_STG 29868
#define PRE_EI  46764
#define PRE_AI  46892
#define PRE_II  47020
#define PRE_AF  47148
#define PRE_B1  47276
#define PRE_B2  47404
#define PRE_B3  47532
#define PRE_B4  47660
#define PRE_B5  47788
#define PRE_R1  47916
#define PRE_SMEM_BYTES (48044 * 4)

__device__ __forceinline__ void gemm_pass(float (&acc)[16][4], const uint32_t* __restrict__ gA,
                                          const uint32_t* sB, int rowoff, int dwu, int u, int r) {
    const uint32_t* Bb = sB + (u + rowoff) * 76 + r;
    for (int kt = 0; kt < 8; kt++) {
        uint32_t a4[4];
        int ai = kt * 1024 + dwu + r;
        a4[0] = gA[ai]; a4[1] = gA[ai + 64]; a4[2] = gA[ai + 4]; a4[3] = gA[ai + 68];
        const uint32_t* Bk = Bb + kt * 8;
#pragma unroll
        for (int nt = 0; nt < 16; nt++)
            mma16(acc[nt], a4, Bk[nt * 608], Bk[nt * 608 + 4]);
    }
}

__device__ __forceinline__ void acc_zero16(float (&acc)[16][4]) {
#pragma unroll
    for (int nt = 0; nt < 16; nt++) {
        acc[nt][0] = 0.f; acc[nt][1] = 0.f; acc[nt][2] = 0.f; acc[nt][3] = 0.f;
    }
}

__device__ __forceinline__ void stage_epi(const float (&acc)[16][4], const float* bs,
                                          int d0, int r, float* stg) {
    float bb0 = bs[d0], bb1 = bs[d0 + 8];
#pragma unroll
    for (int nt = 0; nt < 16; nt++) {
        int t0 = 8 * nt + 2 * r;
        stg[t0 * 132 + d0]           = acc[nt][0] + bb0;
        stg[(t0 + 1) * 132 + d0]     = acc[nt][1] + bb0;
        stg[t0 * 132 + d0 + 8]       = acc[nt][2] + bb1;
        stg[(t0 + 1) * 132 + d0 + 8] = acc[nt][3] + bb1;
    }
}

__device__ __forceinline__ void copy_out(const float* stg, float* __restrict__ dst, int tid) {
#pragma unroll
    for (int j = 0; j < 16; j++) {
        int lin = (j * 256 + tid) * 4;
        int t = lin >> 7, d = lin & 127;
        float4 v = *(const float4*)(stg + t * 132 + d);
        *(float4*)(dst + lin) = v;
    }
}

__global__ void __launch_bounds__(256, 1) k_pre(const int* __restrict__ e_data,
                                                const int* __restrict__ a_data,
                                                const int* __restrict__ it_data,
                                                const int* __restrict__ at_data,
                                                const float* __restrict__ e_w,
                                                const float* __restrict__ at_w,
                                                const float* __restrict__ it_w,
                                                const float* __restrict__ b1,
                                                const float* __restrict__ b2,
                                                const float* __restrict__ b3,
                                                const float* __restrict__ b4,
                                                const float* __restrict__ b5) {
    extern __shared__ uint32_t ps[];
    uint32_t* sB0 = ps + PRE_SB0;
    uint32_t* sB1 = ps + PRE_SB1;
    uint32_t* sB2 = ps + PRE_SB2;
    float* stg  = (float*)(ps + PRE_STG);
    int*   s_ei = (int*)(ps + PRE_EI);
    int*   s_ai = (int*)(ps + PRE_AI);
    int*   s_ii = (int*)(ps + PRE_II);
    float* s_af = (float*)(ps + PRE_AF);
    float* b1s  = (float*)(ps + PRE_B1);
    float* b2s  = (float*)(ps + PRE_B2);
    float* b3s  = (float*)(ps + PRE_B3);
    float* b4s  = (float*)(ps + PRE_B4);
    float* b5s  = (float*)(ps + PRE_B5);
    float* r1s  = (float*)(ps + PRE_R1);

    const int b = blockIdx.x, tid = threadIdx.x;
    const int w = tid >> 5, l = tid & 31, u = l >> 2, r = l & 3;
    const int d0 = 16 * w + u;
    const int dwu = d0 * 8;

    if (tid < 128) {
        s_ei[tid] = e_data[b * SS + tid];
        s_ai[tid] = at_data[b * SS + tid];
        s_ii[tid] = it_data[b * SS + tid];
        s_af[tid] = (float)a_data[b * SS + tid];
        b1s[tid] = b1[tid]; b2s[tid] = b2[tid]; b3s[tid] = b3[tid];
        b4s[tid] = b4[tid]; b5s[tid] = b5[tid];
        r1s[tid] = g_r1[tid];
    }
    for (int i = tid; i < 3 * 76; i += 256) {
        int rr = i / 76, cc = i % 76;
        int wd = (rr == 0 ? 0 : (rr == 1 ? 129 : 130)) * 76 + cc;
        sB0[wd] = 0u; sB1[wd] = 0u; sB2[wd] = 0u;
    }
    __syncthreads();
    for (int i = tid; i < 8192; i += 256) {
        int n = i >> 6, kw = i & 63;
        int wd = (n + 1) * 76 + kw;
        float2 ev = *(const float2*)(e_w + s_ei[n] * DK + 2 * kw);
        float2 av = *(const float2*)(at_w + s_ai[n] * DK + 2 * kw);
        float2 iv = *(const float2*)(it_w + s_ii[n] * DK + 2 * kw);
        sB0[wd] = pack_bf16(ev.x, ev.y);
        sB1[wd] = pack_bf16(av.x, av.y);
        sB2[wd] = pack_bf16(iv.x, iv.y);
    }
    __syncthreads();

    float acc[16][4];
    acc_zero16(acc);
    gemm_pass(acc, g_Wab + SL_W1a * 8192, sB0, 1, dwu, u, r);
    gemm_pass(acc, g_Wab + SL_W1b * 8192, sB1, 1, dwu, u, r);
    __syncthreads();
    {
        float bb0 = b1s[d0], bb1 = b1s[d0 + 8];
        float rr0 = r1s[d0], rr1 = r1s[d0 + 8];
        char* base = (char*)sB1;
        int byc = 4 * (d0 >> 1) + 2 * (d0 & 1);
#pragma unroll
        for (int nt = 0; nt < 16; nt++) {
            int t0 = 8 * nt + 2 * r;
            float a0f = s_af[t0], a1f = s_af[t0 + 1];
            float v00 = acc[nt][0] + bb0 + a0f * rr0;
            float v01 = acc[nt][1] + bb0 + a1f * rr0;
            float v10 = acc[nt][2] + bb1 + a0f * rr1;
            float v11 = acc[nt][3] + bb1 + a1f * rr1;
            int by = (t0 + 1) * 304 + byc;
            *(uint16_t*)(base + by)        = bf16_of(v00);
            *(uint16_t*)(base + by + 304)  = bf16_of(v01);
            *(uint16_t*)(base + by + 16)   = bf16_of(v10);
            *(uint16_t*)(base + by + 320)  = bf16_of(v11);
        }
    }
    __syncthreads();

    acc_zero16(acc);
    gemm_pass(acc, g_Wab + SL_W2a * 8192, sB1, 0, dwu, u, r);
    gemm_pass(acc, g_Wab + SL_W2b * 8192, sB2, 1, dwu, u, r);
    gemm_pass(acc, g_Wab + SL_W2c * 8192, sB1, 1, dwu, u, r);
    stage_epi(acc, b2s, d0, r, stg);
    __syncthreads();
    copy_out(stg, g_P2 + b * SS * DK, tid);
    __syncthreads();

    acc_zero16(acc);
    gemm_pass(acc, g_Wab + SL_W3a * 8192, sB1, 0, dwu, u, r);
    gemm_pass(acc, g_Wab + SL_W3b * 8192, sB2, 1, dwu, u, r);
    gemm_pass(acc, g_Wab + SL_W3c * 8192, sB1, 1, dwu, u, r);
    stage_epi(acc, b3s, d0, r, stg);
    __syncthreads();
    copy_out(stg, g_P3 + b * SS * DK, tid);
    __syncthreads();

    acc_zero16(acc);
    gemm_pass(acc, g_Wab + SL_W4c * 8192, sB2, 1, dwu, u, r);
    stage_epi(acc, b4s, d0, r, stg);
    __syncthreads();
    copy_out(stg, g_P4 + b * SS * DK, tid);
    __syncthreads();

    acc_zero16(acc);
    gemm_pass(acc, g_Wab + SL_W5a * 8192, sB0, 2, dwu, u, r);
    stage_epi(acc, b5s, d0, r, stg);
    __syncthreads();
    copy_out(stg, g_P5 + b * SS * DK, tid);
}

// ---------------- main scan kernel (256 threads, 5 barriers/step) ----------------
// SMEM bytes:
//  Hsb   [0, 38912)          bf16x2 H shadow, word(n,kw)=n*76+kw
//  sWab  [38912, 71680)      W4a A-frag
//  sWz   [71680, 137216)     W2d/W3d stacked 256-row A-frag
//  sW4b  [137216, 169984)    k-pair
//  sW5b  [169984, 202752)    k-pair
//  ht[202752] LG[203264] htb[203776,256) pA3[204032,512) arg[204544,1024)
//  arg2[205568,1024) qe[206592] qn[207104] htp[207616,1024) red[208640,64)
#define HSB_B   0
#define SWAB_B  38912
#define SWZ_B   71680
#define SW4B_B  137216
#define SW5B_B  169984
#define HT_B    202752
#define LG_B    203264
#define HTB_B   203776
#define PA3_B   204032
#define ARG_B   204544
#define ARG2_B  205568
#define QE_B    206592
#define QN_B    207104
#define HTP_B   207616
#define RED_B   208640
#define SMEM_MAIN_BYTES 208704

template<int NT, int NB>
__device__ __forceinline__ void s4a_mma(float (&acc)[2][7][4], const uint32_t* sWab,
                                        const uint32_t* HsbB, int da, int r, int btw) {
    for (int kt = 0; kt < 8; kt++) {
        uint32_t a4[2][4];
#pragma unroll
        for (int a = 0; a < 2; a++) {
            int ab = kt * 1024 + (da + 16 * a) * 8 + r;
            a4[a][0] = sWab[ab];
            a4[a][1] = sWab[ab + 64];
            a4[a][2] = sWab[ab + 4];
            a4[a][3] = sWab[ab + 68];
        }
        const uint32_t* Hk = HsbB + btw + kt * 8;
#pragma unroll
        for (int nt = 0; nt < NT; nt++) {
            uint32_t b0 = Hk[nt * 608];
            uint32_t b1 = Hk[nt * 608 + 4];
            mma16(acc[0][nt], a4[0], b0, b1);
            mma16(acc[1][nt], a4[1], b0, b1);
        }
    }
}

template<int NT, int NB>
__device__ __forceinline__ void epi_step(float (&acc)[2][7][4], float (&Hreg)[2][7][4],
                                         const float* arg, const float* LG,
                                         const float* qe, const float* qn,
                                         char* smc, float* htp,
                                         int da, int h, int r, int hb0) {
    float cs[2][2], lg[2][2];
#pragma unroll
    for (int a = 0; a < 2; a++) {
        cs[a][0] = arg[da + 16 * a] + arg[128 + da + 16 * a];
        cs[a][1] = arg[da + 16 * a + 8] + arg[128 + da + 16 * a + 8];
        lg[a][0] = LG[da + 16 * a];
        lg[a][1] = LG[da + 16 * a + 8];
    }
    float s[2][2] = {{0.f, 0.f}, {0.f, 0.f}};
#pragma unroll
    for (int a = 0; a < 2; a++) {
#pragma unroll
        for (int nt = 0; nt < NT; nt++) {
            int n0 = NB + 8 * nt + 2 * r;
            float2 qev = *(const float2*)(qe + n0);
            float2 qnv2 = *(const float2*)(qn + n0);
            float H00 = qev.x * lg[a][0] + fast_sigmoid(acc[a][nt][0] + cs[a][0]) * Hreg[a][nt][0];
            float H01 = qev.y * lg[a][0] + fast_sigmoid(acc[a][nt][1] + cs[a][0]) * Hreg[a][nt][1];
            float H10 = qev.x * lg[a][1] + fast_sigmoid(acc[a][nt][2] + cs[a][1]) * Hreg[a][nt][2];
            float H11 = qev.y * lg[a][1] + fast_sigmoid(acc[a][nt][3] + cs[a][1]) * Hreg[a][nt][3];
            Hreg[a][nt][0] = H00; Hreg[a][nt][1] = H01;
            Hreg[a][nt][2] = H10; Hreg[a][nt][3] = H11;
            int bn = hb0 + 2432 * nt + 32 * a;
            *(uint16_t*)(smc + bn)       = bf16_of(H00);
            *(uint16_t*)(smc + bn + 16)  = bf16_of(H10);
            *(uint16_t*)(smc + bn + 304) = bf16_of(H01);
            *(uint16_t*)(smc + bn + 320) = bf16_of(H11);
            s[a][0] = fmaf(qnv2.x, H00, fmaf(qnv2.y, H01, s[a][0]));
            s[a][1] = fmaf(qnv2.x, H10, fmaf(qnv2.y, H11, s[a][1]));
        }
    }
#pragma unroll
    for (int a = 0; a < 2; a++) {
        s[a][0] += __shfl_xor_sync(0xffffffffu, s[a][0], 1);
        s[a][0] += __shfl_xor_sync(0xffffffffu, s[a][0], 2);
        s[a][1] += __shfl_xor_sync(0xffffffffu, s[a][1], 1);
        s[a][1] += __shfl_xor_sync(0xffffffffu, s[a][1], 2);
    }
    if (r == 0) {
        htp[h * 128 + da]      = s[0][0];
        htp[h * 128 + da + 8]  = s[0][1];
        htp[h * 128 + da + 16] = s[1][0];
        htp[h * 128 + da + 24] = s[1][1];
    }
}

__global__ void __launch_bounds__(256, 1) k_main(const int* __restrict__ e_data,
                                                 const float* __restrict__ qm,
                                                 const float* __restrict__ h0,
                                                 float* __restrict__ out) {
    extern __shared__ char smc[];
    uint32_t* Hsb  = (uint32_t*)(smc + HSB_B);
    uint32_t* sWab = (uint32_t*)(smc + SWAB_B);
    uint32_t* sWz  = (uint32_t*)(smc + SWZ_B);
    uint32_t* sW4b = (uint32_t*)(smc + SW4B_B);
    uint32_t* sW5b = (uint32_t*)(smc + SW5B_B);
    float*    ht   = (float*)(smc + HT_B);
    float*    LG   = (float*)(smc + LG_B);
    uint32_t* htb  = (uint32_t*)(smc + HTB_B);
    float*    pA3  = (float*)(smc + PA3_B);
    float*    arg  = (float*)(smc + ARG_B);
    float*    arg2 = (float*)(smc + ARG2_B);
    float*    qe   = (float*)(smc + QE_B);
    float*    qn   = (float*)(smc + QN_B);
    float*    htp  = (float*)(smc + HTP_B);
    float*    red  = (float*)(smc + RED_B);

    const int b = blockIdx.x, tid = threadIdx.x;
    const int w = tid >> 5, l = tid & 31;
    const int u = l >> 2, r = l & 3;
    const int g = w & 3;
    const int h = w >> 2;
    const int da = 32 * g + u;
    const int NB = h ? 56 : 0;         // n-range split 7/6 tiles over 104 rows

    // ---- SMEM init ----
    for (int i = tid; i < 8192; i += 256) {
        sWab[i] = g_Wab[SL_W4a * 8192 + i];
        sW4b[i] = g_Wkp[i];
        sW5b[i] = g_Wkp[8192 + i];
    }
    for (int i = tid; i < 16384; i += 256) sWz[i] = g_Wz[i];
    for (int i = tid; i < 8192; i += 256) {
        int n = i >> 6, kw = i & 63;
        float v0 = (n < NQ) ? h0[n * DK + 2 * kw] : 0.f;
        float v1 = (n < NQ) ? h0[n * DK + 2 * kw + 1] : 0.f;
        Hsb[n * 76 + kw] = pack_bf16(v0, v1);
    }
    float Hreg[2][7][4];
#pragma unroll
    for (int a = 0; a < 2; a++)
#pragma unroll
        for (int nt = 0; nt < 7; nt++) {
            int n0 = NB + 8 * nt + 2 * r;
            int dd = da + 16 * a;
            bool ok0 = (h == 0 || nt < 6);
            Hreg[a][nt][0] = (ok0 && n0 < NQ)     ? h0[n0 * DK + dd]           : 0.f;
            Hreg[a][nt][1] = (ok0 && n0 + 1 < NQ) ? h0[(n0 + 1) * DK + dd]     : 0.f;
            Hreg[a][nt][2] = (ok0 && n0 < NQ)     ? h0[n0 * DK + dd + 8]       : 0.f;
            Hreg[a][nt][3] = (ok0 && n0 + 1 < NQ) ? h0[(n0 + 1) * DK + dd + 8] : 0.f;
        }

    int eA = e_data[b * SS];
    int eB = e_data[b * SS + 1];
    if (tid < 128) {
        qe[tid] = (tid < NQ) ? qm[eA * NQ + tid] : 0.f;
        qn[tid] = 0.f;
    }
    __syncthreads();
    if (tid < 32) {
        float v = 0.f;
        for (int n = tid; n < NQ; n += 32) v += qe[n];
#pragma unroll
        for (int oo = 16; oo; oo >>= 1) v += __shfl_xor_sync(0xffffffffu, v, oo);
        if (tid == 0) red[0] = v;
    }
    __syncthreads();
    if (tid < 128) {
        float a = 0.f;
        for (int n = 0; n < NQ; n++) a += qe[n] * h0[n * DK + tid];
        float v = a / red[0];
        ht[tid] = v;
        *(uint16_t*)((char*)htb + 2 * tid) = bf16_of(v);
    }
    if (tid == 0) out[b * SS] = 0.f;

    // ---- prefetch step-0 operands ----
    float p_a = 0.f, p4v = 0.f, p5v = 0.f, p5A = 0.f, qv = 0.f, qnv = 0.f;
    {
        const int base = (b * SS) * DK;
        if (tid < 128) {
            p_a = g_P2[base + tid];
            p4v = g_P4[base + tid];
            p5v = g_P5[base + tid];
            qv  = (tid < NQ) ? qm[eA * NQ + tid] : 0.f;
        } else {
            p_a = g_P3[base + tid - 128];
            int m = tid - 128;
            qnv = (m < NQ) ? qm[eB * NQ + m] : 0.f;
        }
    }

    const int btw = u * 76 + r;
    const uint32_t* HsbB = Hsb + NB * 76;
    const int db = 64 * g + 4 * (u >> 1) + 2 * (u & 1);
    const int hb0 = 304 * (NB + 2 * r) + db;
    const int zbase = 256 * w + 8 * u + r;

    // ---- scan ----
    for (int t = 0; t < SS - 1; t++) {
        __syncthreads();                        // sync1
        if (tid < 128) qe[tid] = qv;
        else { qn[tid - 128] = qnv; pA3[tid - 128] = p_a; }

        // Phase A1: S1-MMA  arg[0..255] = Wz . ht
        {
            float z0[4] = {0.f, 0.f, 0.f, 0.f};
            float z1[4] = {0.f, 0.f, 0.f, 0.f};
            for (int kt = 0; kt < 8; kt++) {
                const uint32_t* Wk = sWz + kt * 2048;
                uint32_t az0[4], az1[4];
                az0[0] = Wk[zbase];        az0[1] = Wk[zbase + 64];
                az0[2] = Wk[zbase + 4];    az0[3] = Wk[zbase + 68];
                az1[0] = Wk[zbase + 128];  az1[1] = Wk[zbase + 192];
                az1[2] = Wk[zbase + 132];  az1[3] = Wk[zbase + 196];
                uint32_t hb_0 = (u == 0) ? htb[kt * 8 + r] : 0u;
                uint32_t hb_1 = (u == 0) ? htb[kt * 8 + r + 4] : 0u;
                mma16(z0, az0, hb_0, hb_1);
                mma16(z1, az1, hb_0, hb_1);
            }
            if (r == 0) {
                arg[32 * w + u]      = z0[0];
                arg[32 * w + u + 8]  = z0[2];
                arg[32 * w + 16 + u] = z1[0];
                arg[32 * w + 24 + u] = z1[2];
            }
        }

        // Phase A2: S6-prev matvec -> arg2 (uses ht from prev step; out index t)
        {
            int d = tid & 127, hh = tid >> 7;
            const uint32_t* Wp = sW5b + hh * 32 * 128;
            const float* hp = ht + hh * 64;
            float a0 = hh ? 0.f : p5A, a1 = 0.f, a2 = 0.f, a3 = 0.f;
#pragma unroll 8
            for (int kw = 0; kw < 32; kw += 2) {
                uint32_t w0 = Wp[kw * 128 + d];
                uint32_t w1 = Wp[(kw + 1) * 128 + d];
                float4 hv = *(const float4*)(hp + 2 * kw);
                a0 = fmaf(hv.x, bf_lo(w0), a0);
                a1 = fmaf(hv.y, bf_hi(w0), a1);
                a2 = fmaf(hv.z, bf_lo(w1), a2);
                a3 = fmaf(hv.w, bf_hi(w1), a3);
            }
            arg2[tid] = (a0 + a1) + (a2 + a3);
        }

        // Phase A3: S4a tensor GEMM (7/6 n-split)
        float acc[2][7][4];
#pragma unroll
        for (int a = 0; a < 2; a++)
#pragma unroll
            for (int nt = 0; nt < 7; nt++) {
                acc[a][nt][0] = 0.f; acc[a][nt][1] = 0.f;
                acc[a][nt][2] = 0.f; acc[a][nt][3] = 0.f;
            }
        if (h == 0) s4a_mma<7, 0>(acc, sWab, HsbB, da, r, btw);
        else        s4a_mma<6, 56>(acc, sWab, HsbB, da, r, btw);
        __syncthreads();                        // sync2

        // S2: LG (tid<128) || qn-sum (w4) || S6-prev reduce (w5)
        if (tid < 128) {
            float lg = fast_tanh(arg[tid] + p_a);
            float gl = fast_sigmoid(arg[128 + tid] + pA3[tid]);
            LG[tid] = gl * (lg + 1.f) * 0.5f;
        } else if (tid < 160) {
            int lane = tid - 128;
            float v = 0.f;
            for (int n = lane; n < NQ; n += 32) v += qn[n];
#pragma unroll
            for (int oo = 16; oo; oo >>= 1) v += __shfl_xor_sync(0xffffffffu, v, oo);
            if (lane == 0) red[0] = v;
        } else if (tid < 192) {
            int lane = tid - 160;
            float v = 0.f;
#pragma unroll
            for (int j = 0; j < 4; j++) {
                int d = lane + 32 * j;
                v += fast_sigmoid(arg2[d] + arg2[128 + d]);
            }
#pragma unroll
            for (int oo = 16; oo; oo >>= 1) v += __shfl_xor_sync(0xffffffffu, v, oo);
            if (lane == 0) red[8] = v;
        }
        __syncthreads();                        // sync3

        // S3: split-k partials of P4 + LG @ W4b^T -> arg  (+ out[t] write)
        if (tid == 0 && t >= 1)
            out[b * SS + t] = red[8] * (1.0f / 128.0f);
        {
            int d = tid & 127, hh = tid >> 7;
            const uint32_t* Wp = sW4b + hh * 32 * 128;
            const float* lgp = LG + hh * 64;
            float a0 = hh ? 0.f : p4v, a1 = 0.f, a2 = 0.f, a3 = 0.f;
#pragma unroll 8
            for (int kw = 0; kw < 32; kw += 2) {
                uint32_t w0 = Wp[kw * 128 + d];
                uint32_t w1 = Wp[(kw + 1) * 128 + d];
                float4 lv = *(const float4*)(lgp + 2 * kw);
                a0 = fmaf(lv.x, bf_lo(w0), a0);
                a1 = fmaf(lv.y, bf_hi(w0), a1);
                a2 = fmaf(lv.z, bf_lo(w1), a2);
                a3 = fmaf(lv.w, bf_hi(w1), a3);
            }
            arg[tid] = (a0 + a1) + (a2 + a3);
        }
        __syncthreads();                        // sync4

        // S4b epilogue
        if (h == 0) epi_step<7, 0>(acc, Hreg, arg, LG, qe, qn, smc, htp, da, h, r, hb0);
        else        epi_step<6, 56>(acc, Hreg, arg, LG, qe, qn, smc, htp, da, h, r, hb0);
        __syncthreads();                        // sync5

        // ht + htb update (fused)
        if (tid < 128) {
            float v = (htp[tid] + htp[128 + tid]) / red[0];
            ht[tid] = v;
            *(uint16_t*)((char*)htb + 2 * tid) = bf16_of(v);
        }

        // prefetch next step operands + P5 rotation
        p5A = p5v;
        {
            int t2 = (t + 2 < SS) ? t + 2 : SS - 1;
            eA = eB;
            eB = e_data[b * SS + t2];
            const int base2 = (b * SS + t + 1) * DK;
            if (tid < 128) {
                p_a = g_P2[base2 + tid];
                p4v = g_P4[base2 + tid];
                p5v = g_P5[base2 + tid];
                qv  = (tid < NQ) ? qm[eA * NQ + tid] : 0.f;
            } else {
                p_a = g_P3[base2 + tid - 128];
                int m = tid - 128;
                qnv = (m < NQ) ? qm[eB * NQ + m] : 0.f;
            }
        }
        // loop back: sync1 orders ht/htb/Hsb for next Phase A
    }

    // ---- tail: y for last step -> out[127] ----
    __syncthreads();
    {
        int d = tid & 127, hh = tid >> 7;
        const uint32_t* Wp = sW5b + hh * 32 * 128;
        const float* hp = ht + hh * 64;
        float a0 = hh ? 0.f : p5A, a1 = 0.f, a2 = 0.f, a3 = 0.f;
#pragma unroll 8
        for (int kw = 0; kw < 32; kw += 2) {
            uint32_t w0 = Wp[kw * 128 + d];
            uint32_t w1 = Wp[(kw + 1) * 128 + d];
            float4 hv = *(const float4*)(hp + 2 * kw);
            a0 = fmaf(hv.x, bf_lo(w0), a0);
            a1 = fmaf(hv.y, bf_hi(w0), a1);
            a2 = fmaf(hv.z, bf_lo(w1), a2);
            a3 = fmaf(hv.w, bf_hi(w1), a3);
        }
        arg2[tid] = (a0 + a1) + (a2 + a3);
    }
    __syncthreads();
    if (tid < 32) {
        float v = 0.f;
#pragma unroll
        for (int j = 0; j < 4; j++) {
            int d = tid + 32 * j;
            v += fast_sigmoid(arg2[d] + arg2[128 + d]);
        }
#pragma unroll
        for (int oo = 16; oo; oo >>= 1) v += __shfl_xor_sync(0xffffffffu, v, oo);
        if (tid == 0) {
            out[b * SS + SS - 2] = red[8] * (1.0f / 128.0f);   // y_125 -> out[126]
            out[b * SS + SS - 1] = v * (1.0f / 128.0f);        // y_126 -> out[127]
        }
    }
}

// ---------------- host launcher ----------------
extern "C" void kernel_launch(void* const* d_in, const int* in_sizes, int n_in,
                              void* d_out, int out_size) {
    (void)in_sizes; (void)n_in; (void)out_size;
    const int*   e_data  = (const int*)d_in[0];
    const int*   a_data  = (const int*)d_in[1];
    const int*   it_data = (const int*)d_in[2];
    const int*   at_data = (const int*)d_in[3];
    const float* qm      = (const float*)d_in[4];
    const float* e_w     = (const float*)d_in[5];
    const float* at_w    = (const float*)d_in[6];
    const float* it_w    = (const float*)d_in[7];
    const float* h0      = (const float*)d_in[8];
    const float* W1      = (const float*)d_in[9];
    const float* b1      = (const float*)d_in[10];
    const float* W2      = (const float*)d_in[11];
    const float* b2      = (const float*)d_in[12];
    const float* W3      = (const float*)d_in[13];
    const float* b3      = (const float*)d_in[14];
    const float* W4      = (const float*)d_in[15];
    const float* b4      = (const float*)d_in[16];
    const float* W5      = (const float*)d_in[17];
    const float* b5      = (const float*)d_in[18];
    float* out = (float*)d_out;

    cudaFuncSetAttribute(k_pre,  cudaFuncAttributeMaxDynamicSharedMemorySize, PRE_SMEM_BYTES);
    cudaFuncSetAttribute(k_main, cudaFuncAttributeMaxDynamicSharedMemorySize, SMEM_MAIN_BYTES);

    k_transpose<<<15, 256>>>(W1, W2, W3, W4, W5);
    k_pre<<<BB, 256, PRE_SMEM_BYTES>>>(e_data, a_data, it_data, at_data,
                                       e_w, at_w, it_w, b1, b2, b3, b4, b5);
    k_main<<<BB, 256, SMEM_MAIN_BYTES>>>(e_data, qm, h0, out);
    (void)W4;
}